// round 15
// baseline (speedup 1.0000x reference)
#include <cuda_runtime.h>
#include <cuda_bf16.h>
#include <math.h>

// Problem constants
#define N_ROWS 16384
#define F_FEAT 39
#define V_SZ   100000
#define E_DIM  16
#define HIDDEN 400
#define K1     (F_FEAT*E_DIM)   // 624
#define BN_EPS 1e-5f
#define MBLK   (N_ROWS/256)     // 64 row-blocks in the GEMM grid
#define RS     24               // smem row stride in ushort (48B, conflict-free)

typedef unsigned short ushort_t;

// ---------------- scratch (allocation-free) ----------------
__device__ __align__(16) ushort_t g_H0h[(size_t)N_ROWS * K1];     // bf16 H0 (hi only)
__device__ __align__(16) ushort_t g_Xh[(size_t)N_ROWS * HIDDEN];  // bf16 act(layer in)
__device__ __align__(16) float    g_HA[(size_t)N_ROWS * HIDDEN];  // GEMM out (pre-BN)
__device__ __align__(16) ushort_t g_W1h[HIDDEN * K1];             // W bf16 hi/lo planes
__device__ __align__(16) ushort_t g_W1l[HIDDEN * K1];
__device__ __align__(16) ushort_t g_W2h[HIDDEN * HIDDEN];
__device__ __align__(16) ushort_t g_W2l[HIDDEN * HIDDEN];
__device__ __align__(16) ushort_t g_W3h[HIDDEN * HIDDEN];
__device__ __align__(16) ushort_t g_W3l[HIDDEN * HIDDEN];
__device__ __align__(16) float    g_parts[HIDDEN * MBLK];   // TRANSPOSED: [col][block]
__device__ __align__(16) float    g_partq[HIDDEN * MBLK];   // TRANSPOSED: [col][block]
__device__ __align__(16) float    g_sa[HIDDEN];
__device__ __align__(16) float    g_sc[HIDDEN];

__device__ __forceinline__ unsigned smem_u32(const void* p) {
    unsigned a;
    asm("{ .reg .u64 t; cvta.to.shared.u64 t, %1; cvt.u32.u64 %0, t; }" : "=r"(a) : "l"(p));
    return a;
}

#define LDSM_X4(r0, r1, r2, r3, addr) \
    asm volatile("ldmatrix.sync.aligned.m8n8.x4.shared.b16 {%0,%1,%2,%3}, [%4];" \
                 : "=r"(r0), "=r"(r1), "=r"(r2), "=r"(r3) : "r"(addr))

#define MMA_BF16(cc, a, b0, b1) \
    asm volatile("mma.sync.aligned.m16n8k16.row.col.f32.bf16.bf16.f32 " \
                 "{%0,%1,%2,%3},{%4,%5,%6,%7},{%8,%9},{%0,%1,%2,%3};" \
                 : "+f"((cc)[0]), "+f"((cc)[1]), "+f"((cc)[2]), "+f"((cc)[3]) \
                 : "r"((a)[0]), "r"((a)[1]), "r"((a)[2]), "r"((a)[3]), \
                   "r"(b0), "r"(b1))

#define CP_ASYNC16(dst, src) \
    asm volatile("cp.async.cg.shared.global [%0], [%1], 16;" :: "r"(dst), "l"(src))
#define CP_COMMIT()  asm volatile("cp.async.commit_group;" ::: "memory")
#define CP_WAIT1()   asm volatile("cp.async.wait_group 1;" ::: "memory")

__device__ __forceinline__ unsigned pack2(__nv_bfloat16 a, __nv_bfloat16 b) {
    return ((unsigned)__bfloat16_as_ushort(b) << 16) | (unsigned)__bfloat16_as_ushort(a);
}
__device__ __forceinline__ void split4(float4 x, unsigned& h0, unsigned& h1,
                                       unsigned& l0, unsigned& l1) {
    __nv_bfloat16 a = __float2bfloat16(x.x), b = __float2bfloat16(x.y);
    __nv_bfloat16 c = __float2bfloat16(x.z), d = __float2bfloat16(x.w);
    h0 = pack2(a, b); h1 = pack2(c, d);
    l0 = pack2(__float2bfloat16(x.x - __bfloat162float(a)),
               __float2bfloat16(x.y - __bfloat162float(b)));
    l1 = pack2(__float2bfloat16(x.z - __bfloat162float(c)),
               __float2bfloat16(x.w - __bfloat162float(d)));
}
__device__ __forceinline__ void hi4(float4 x, unsigned& h0, unsigned& h1) {
    h0 = pack2(__float2bfloat16(x.x), __float2bfloat16(x.y));
    h1 = pack2(__float2bfloat16(x.z), __float2bfloat16(x.w));
}
__device__ __forceinline__ float4 bn_relu4(float4 x, int k) {
    float4 s = *(const float4*)&g_sa[k];
    float4 c = *(const float4*)&g_sc[k];
    x.x = fmaxf(fmaf(s.x, x.x, c.x), 0.f);
    x.y = fmaxf(fmaf(s.y, x.y, c.y), 0.f);
    x.z = fmaxf(fmaf(s.z, x.z, c.z), 0.f);
    x.w = fmaxf(fmaf(s.w, x.w, c.w), 0.f);
    return x;
}

// ---------------------------------------------------------------------------
// Kernel 0: convert all three weight matrices to bf16 hi/lo planes (one launch).
// ---------------------------------------------------------------------------
#define W1Q (HIDDEN*K1/4)        // 62400 float4s
#define W2Q (HIDDEN*HIDDEN/4)    // 40000
#define WTOTQ (W1Q + 2*W2Q)      // 142400
__global__ __launch_bounds__(256)
void convw_all_kernel(const float* __restrict__ W1,
                      const float* __restrict__ W2,
                      const float* __restrict__ W3)
{
    for (int i = blockIdx.x * blockDim.x + threadIdx.x; i < WTOTQ;
         i += gridDim.x * blockDim.x) {
        const float* src;
        ushort_t *dh, *dl;
        int j;
        if (i < W1Q)               { src = W1; dh = g_W1h; dl = g_W1l; j = i; }
        else if (i < W1Q + W2Q)    { src = W2; dh = g_W2h; dl = g_W2l; j = i - W1Q; }
        else                       { src = W3; dh = g_W3h; dl = g_W3l; j = i - W1Q - W2Q; }
        float4 x = ((const float4*)src)[j];
        unsigned h0, h1, l0, l1;
        split4(x, h0, h1, l0, l1);
        ((uint2*)dh)[j] = make_uint2(h0, h1);
        ((uint2*)dl)[j] = make_uint2(l0, l1);
    }
}

// ---------------------------------------------------------------------------
// Kernel 1: gather + FM terms + normalize; writes H0 as bf16 (hi only).
// ---------------------------------------------------------------------------
__global__ __launch_bounds__(256)
void gather_fm_kernel(const int* __restrict__ Xi, const float* __restrict__ Xv,
                      const float* __restrict__ emb1, const float* __restrict__ emb2,
                      const float* __restrict__ bias, float* __restrict__ out)
{
    const int e = threadIdx.x;
    const int r = threadIdx.y;
    const int n = blockIdx.x * 16 + r;

    float arr[F_FEAT];
    float sumsq = 0.f;
    #pragma unroll
    for (int f = 0; f < F_FEAT; f++) {
        int idx = Xi[(size_t)n * F_FEAT + f];
        float xvf = Xv[(size_t)n * F_FEAT + f];
        float v = emb2[((size_t)f * V_SZ + (size_t)idx) * E_DIM + e] * xvf;
        arr[f] = v;
        sumsq = fmaf(v, v, sumsq);
    }
    float inv = 1.0f / fmaxf(sqrtf(sumsq), 1e-12f);
    float s = 0.f, ss = 0.f;
    #pragma unroll
    for (int f = 0; f < F_FEAT; f++) {
        float w = arr[f] * inv;
        s += w; ss = fmaf(w, w, ss);
        g_H0h[(size_t)n * K1 + f * E_DIM + e] =
            __bfloat16_as_ushort(__float2bfloat16(w));
    }
    float val = 0.5f * (s * s - ss);
    for (int f = e; f < F_FEAT; f += 16) {
        int idx = Xi[(size_t)n * F_FEAT + f];
        val = fmaf(emb1[(size_t)f * V_SZ + (size_t)idx], Xv[(size_t)n * F_FEAT + f], val);
    }
    #pragma unroll
    for (int off = 8; off > 0; off >>= 1)
        val += __shfl_down_sync(0xffffffffu, val, off, 16);
    if (e == 0) out[n] = val + bias[0];
}

// ---------------------------------------------------------------------------
// GEMM body, templated on tile width NT (cols = NT*8). All columns valid by
// construction (no guards): wide blocks cover 0..383, narrow block 384..399.
// ---------------------------------------------------------------------------
template<int KDIM, int NT>
__device__ __forceinline__ void gemm_body(
    const ushort_t* __restrict__ Ap, const ushort_t* __restrict__ Wh,
    const ushort_t* __restrict__ Wl, const float* __restrict__ bvec,
    ushort_t (*sA)[256*RS], ushort_t (*sBh)[64*RS], ushort_t (*sBl)[64*RS],
    int m0, int n0)
{
    const int tid   = threadIdx.x;
    const int lane  = tid & 31;
    const int warp  = tid >> 5;     // m-warp, 0..7

    // staging mapping
    const int arow = tid;                 // A row 0..255, 32B per chunk
    const int brow = tid >> 2;            // B row
    const int bpl  = (tid >> 1) & 1;      // B plane 0=hi,1=lo
    const int bsg  = tid & 1;             // 16B segment
    const bool bstage = tid < NT * 32;    // NT*8 rows x 2 planes x 2 segs
    const ushort_t* aph = Ap + (size_t)(m0 + arow) * KDIM;
    const ushort_t* bpp = (bpl ? Wl : Wh)
                        + (size_t)(n0 + (bstage ? brow : 0)) * KDIM;

    const unsigned uA[2]  = { smem_u32(sA[0]),  smem_u32(sA[1])  };
    const unsigned uBh[2] = { smem_u32(sBh[0]), smem_u32(sBh[1]) };
    const unsigned uBl[2] = { smem_u32(sBl[0]), smem_u32(sBl[1]) };
    const unsigned uBd[2] = { bpl ? uBl[0] : uBh[0], bpl ? uBl[1] : uBh[1] };

    // ldmatrix per-thread base offsets (bytes), row stride 48B (conflict-free)
    const unsigned aoff = (warp * 32 + (lane & 15)) * 48 + (lane >> 4) * 16;
    const unsigned boff = (((lane >> 4) << 3) + (lane & 7)) * 48
                        + ((lane >> 3) & 1) * 16;

    float c[2][NT][4];
    #pragma unroll
    for (int mt = 0; mt < 2; mt++)
        #pragma unroll
        for (int nt = 0; nt < NT; nt++)
            #pragma unroll
            for (int i = 0; i < 4; i++) c[mt][nt][i] = 0.f;

    const int nch = KDIM / 16;   // KDIM multiple of 16: no tails anywhere

    // ---- prologue: stage chunks 0 and 1 ----
    #pragma unroll
    for (int p = 0; p < 2; p++) {
        int kb = p * 16;
        CP_ASYNC16(uA[p] + arow * 48,      aph + kb);
        CP_ASYNC16(uA[p] + arow * 48 + 16, aph + kb + 8);
        if (bstage) CP_ASYNC16(uBd[p] + brow * 48 + bsg * 16, bpp + kb + bsg * 8);
        CP_COMMIT();
    }

    for (int ch = 0; ch < nch; ch++) {
        const int buf = ch & 1;
        CP_WAIT1();          // chunk ch arrived (ch+1 may still be in flight)
        __syncthreads();

        // ---- compute chunk ch ----
        {
            unsigned ah[2][4], bh[NT][2], bl[NT][2];
            LDSM_X4(ah[0][0], ah[0][1], ah[0][2], ah[0][3], uA[buf] + aoff);
            LDSM_X4(ah[1][0], ah[1][1], ah[1][2], ah[1][3], uA[buf] + aoff + 16 * 48);
            #pragma unroll
            for (int g = 0; g < NT / 2; g++) {
                LDSM_X4(bh[2*g][0], bh[2*g][1], bh[2*g+1][0], bh[2*g+1][1],
                        uBh[buf] + boff + g * 16 * 48);
                LDSM_X4(bl[2*g][0], bl[2*g][1], bl[2*g+1][0], bl[2*g+1][1],
                        uBl[buf] + boff + g * 16 * 48);
            }
            #pragma unroll
            for (int mt = 0; mt < 2; mt++)
                #pragma unroll
                for (int nt = 0; nt < NT; nt++) {
                    MMA_BF16(c[mt][nt], ah[mt], bh[nt][0], bh[nt][1]);
                    MMA_BF16(c[mt][nt], ah[mt], bl[nt][0], bl[nt][1]);
                }
        }
        __syncthreads();     // all reads of buf done before restaging it

        // ---- stage chunk ch+2 into buf ----
        if (ch + 2 < nch) {
            int kb = (ch + 2) * 16;
            CP_ASYNC16(uA[buf] + arow * 48,      aph + kb);
            CP_ASYNC16(uA[buf] + arow * 48 + 16, aph + kb + 8);
            if (bstage) CP_ASYNC16(uBd[buf] + brow * 48 + bsg * 16, bpp + kb + bsg * 8);
        }
        CP_COMMIT();         // one group per iteration keeps wait_group 1 aligned
    }

    // ---------------- Epilogue: bias, store, per-column stats ----------------
    const int gq = lane >> 2;   // 0..7 (row group)
    const int gr = lane & 3;    // 0..3 (col pair)

    float sS[NT][2], sQ[NT][2];
    #pragma unroll
    for (int nt = 0; nt < NT; nt++) { sS[nt][0] = sS[nt][1] = 0.f; sQ[nt][0] = sQ[nt][1] = 0.f; }

    #pragma unroll
    for (int nt = 0; nt < NT; nt++) {
        int col = n0 + nt * 8 + 2 * gr;
        float bb0 = bvec[col];
        float bb1 = bvec[col + 1];
        #pragma unroll
        for (int mt = 0; mt < 2; mt++) {
            int r0 = m0 + warp * 32 + mt * 16 + gq;
            float v00 = c[mt][nt][0] + bb0;
            float v01 = c[mt][nt][1] + bb1;
            float v10 = c[mt][nt][2] + bb0;
            float v11 = c[mt][nt][3] + bb1;
            *(float2*)&g_HA[(size_t)r0 * HIDDEN + col]       = make_float2(v00, v01);
            *(float2*)&g_HA[(size_t)(r0 + 8) * HIDDEN + col] = make_float2(v10, v11);
            sS[nt][0] += v00 + v10;
            sS[nt][1] += v01 + v11;
            sQ[nt][0] = fmaf(v00, v00, fmaf(v10, v10, sQ[nt][0]));
            sQ[nt][1] = fmaf(v01, v01, fmaf(v11, v11, sQ[nt][1]));
        }
    }
    #pragma unroll
    for (int nt = 0; nt < NT; nt++)
        #pragma unroll
        for (int p = 0; p < 2; p++) {
            #pragma unroll
            for (int off = 4; off <= 16; off <<= 1) {
                sS[nt][p] += __shfl_xor_sync(0xffffffffu, sS[nt][p], off);
                sQ[nt][p] += __shfl_xor_sync(0xffffffffu, sQ[nt][p], off);
            }
        }
    __syncthreads();   // compute done -> alias sA as reduction scratch
    float* redS = (float*)sA[0];
    float* redQ = (float*)sA[0] + 8 * NT * 8;
    if (gq == 0) {
        #pragma unroll
        for (int nt = 0; nt < NT; nt++)
            #pragma unroll
            for (int p = 0; p < 2; p++) {
                int cl = nt * 8 + 2 * gr + p;
                redS[warp * (NT * 8) + cl] = sS[nt][p];
                redQ[warp * (NT * 8) + cl] = sQ[nt][p];
            }
    }
    __syncthreads();
    if (tid < NT * 8) {
        int col = n0 + tid;
        float s = 0.f, q = 0.f;
        #pragma unroll
        for (int w = 0; w < 8; w++) {
            s += redS[w * (NT * 8) + tid];
            q += redQ[w * (NT * 8) + tid];
        }
        // TRANSPOSED partials: [col][block] for coalesced finalize reads
        g_parts[(size_t)col * MBLK + blockIdx.x] = s;
        g_partq[(size_t)col * MBLK + blockIdx.x] = q;
    }
}

// ---------------------------------------------------------------------------
// Kernel 2: bf16 ldmatrix GEMM, cp.async double-buffered (2-stage, K-chunk 16).
// grid (MBLK, 7): blocks 0-5 are 64-col tiles (cols 0..383), block 6 is a
// 16-col tile (cols 384..399). Exact coverage -> no guards, no dead MMAs.
// ---------------------------------------------------------------------------
template<int KDIM, int SRC, int WSEL>
__global__ __launch_bounds__(256, 2)
void gemm_db(const float* __restrict__ bvec)
{
    __shared__ __align__(16) ushort_t sA [2][256 * RS];
    __shared__ __align__(16) ushort_t sBh[2][64 * RS];
    __shared__ __align__(16) ushort_t sBl[2][64 * RS];

    const ushort_t* Ap = (SRC == 0) ? g_H0h : g_Xh;
    const ushort_t* Wh = (WSEL == 1) ? g_W1h : ((WSEL == 2) ? g_W2h : g_W3h);
    const ushort_t* Wl = (WSEL == 1) ? g_W1l : ((WSEL == 2) ? g_W2l : g_W3l);

    const int m0 = blockIdx.x * 256;
    if (blockIdx.y < 6)
        gemm_body<KDIM, 8>(Ap, Wh, Wl, bvec, sA, sBh, sBl, m0, blockIdx.y * 64);
    else
        gemm_body<KDIM, 2>(Ap, Wh, Wl, bvec, sA, sBh, sBl, m0, 384);
}

// ---------------------------------------------------------------------------
// Kernel 3: finalize BN stats -> folded scale/shift. Warp per column.
// grid = 50, block = 256 (8 warps). Partials transposed: 64 consecutive floats
// per column -> fully coalesced (2 cache lines per warp).
// ---------------------------------------------------------------------------
__global__ __launch_bounds__(256)
void finalize_kernel(const float* __restrict__ g, const float* __restrict__ bt)
{
    const int col  = blockIdx.x * 8 + (threadIdx.x >> 5);
    const int lane = threadIdx.x & 31;
    const float* ps = &g_parts[(size_t)col * MBLK];
    const float* pq = &g_partq[(size_t)col * MBLK];
    float s = ps[lane] + ps[lane + 32];
    float q = pq[lane] + pq[lane + 32];
    #pragma unroll
    for (int off = 16; off > 0; off >>= 1) {
        s += __shfl_xor_sync(0xffffffffu, s, off);
        q += __shfl_xor_sync(0xffffffffu, q, off);
    }
    if (lane == 0) {
        float mu  = s * (1.0f / N_ROWS);
        float var = q * (1.0f / N_ROWS) - mu * mu;
        float a = g[col] * rsqrtf(var + BN_EPS);
        g_sa[col] = a;
        g_sc[col] = fmaf(-a, mu, bt[col]);
    }
}

// ---------------------------------------------------------------------------
// Kernel 4: BN + ReLU + bf16 round, g_HA -> g_Xh.
// ---------------------------------------------------------------------------
__global__ __launch_bounds__(256)
void bnsplit_kernel()
{
    const int total = N_ROWS * HIDDEN / 4;
    int i = blockIdx.x * blockDim.x + threadIdx.x;
    if (i < total) {
        float4 v = ((const float4*)g_HA)[i];
        int c0 = (i % (HIDDEN / 4)) * 4;
        v = bn_relu4(v, c0);
        unsigned h0, h1;
        hi4(v, h0, h1);
        ((uint2*)g_Xh)[i] = make_uint2(h0, h1);
    }
}

// ---------------------------------------------------------------------------
// Kernel 5: final BN + ReLU fused with row-sum (float4 loads), adds into out.
// ---------------------------------------------------------------------------
__global__ __launch_bounds__(256)
void bn_relu_rowsum_kernel(float* __restrict__ out)
{
    const int warp = threadIdx.x >> 5;
    const int lane = threadIdx.x & 31;
    const int n = (blockIdx.x << 3) + warp;
    const float4* row = (const float4*)(g_HA + (size_t)n * HIDDEN);  // 100 float4
    float s = 0.f;
    #pragma unroll
    for (int q = lane; q < HIDDEN / 4; q += 32) {
        float4 v = row[q];
        int c0 = q * 4;
        v = bn_relu4(v, c0);
        s += (v.x + v.y) + (v.z + v.w);
    }
    #pragma unroll
    for (int off = 16; off > 0; off >>= 1)
        s += __shfl_xor_sync(0xffffffffu, s, off);
    if (lane == 0) out[n] += s;
}

// ---------------------------------------------------------------------------
extern "C" void kernel_launch(void* const* d_in, const int* in_sizes, int n_in,
                              void* d_out, int out_size)
{
    const int* Xi        = (const int*)d_in[0];
    const float* Xv      = (const float*)d_in[1];
    const float* emb1    = (const float*)d_in[2];
    const float* emb2    = (const float*)d_in[3];
    const float* W1      = (const float*)d_in[4];
    const float* b1      = (const float*)d_in[5];
    const float* g1      = (const float*)d_in[6];
    const float* bt1     = (const float*)d_in[7];
    const float* W2      = (const float*)d_in[8];
    const float* b2      = (const float*)d_in[9];
    const float* g2      = (const float*)d_in[10];
    const float* bt2     = (const float*)d_in[11];
    const float* W3      = (const float*)d_in[12];
    const float* b3      = (const float*)d_in[13];
    const float* g3      = (const float*)d_in[14];
    const float* bt3     = (const float*)d_in[15];
    const float* bias    = (const float*)d_in[16];
    float* out = (float*)d_out;

    // Pre-convert all weights to bf16 hi/lo planes (single launch)
    convw_all_kernel<<<(WTOTQ + 255) / 256, 256>>>(W1, W2, W3);

    gather_fm_kernel<<<N_ROWS / 16, dim3(16, 16)>>>(Xi, Xv, emb1, emb2, bias, out);

    dim3 ggrid(MBLK, 7);   // (64, 7): 6 wide tiles + 1 narrow tile
    const int bs_grid = (N_ROWS * HIDDEN / 4 + 255) / 256;

    gemm_db<K1, 0, 1><<<ggrid, 256>>>(b1);
    finalize_kernel<<<HIDDEN / 8, 256>>>(g1, bt1);
    bnsplit_kernel<<<bs_grid, 256>>>();

    gemm_db<HIDDEN, 1, 2><<<ggrid, 256>>>(b2);
    finalize_kernel<<<HIDDEN / 8, 256>>>(g2, bt2);
    bnsplit_kernel<<<bs_grid, 256>>>();

    gemm_db<HIDDEN, 1, 3><<<ggrid, 256>>>(b3);
    finalize_kernel<<<HIDDEN / 8, 256>>>(g3, bt3);

    bn_relu_rowsum_kernel<<<N_ROWS / 8, 256>>>(out);
}